// round 11
// baseline (speedup 1.0000x reference)
#include <cuda_runtime.h>

#define IN_DIM   8192
#define OUT_DIM  16384
#define TOPK     327
#define ROW_SPLITS 37                 // 16 * 37 = 592 = 4 * 148 SMs → one wave
#define ROWS_PER_SPLIT 222            // ceil(8192 / 37)
#define COL_BLOCKS 16
#define CNT_ONE  (1u << 20)
#define VAL_MASK 0xFFFFFu
#define BBLK     256                  // finalize blocks
#define BCOLS    (OUT_DIM / BBLK)     // 64 columns per finalize block

__device__ unsigned g_overlap[OUT_DIM];  // packed [cnt|val]; self-resets to 0 every launch
__device__ int      g_final[OUT_DIM];    // final overlaps; fully rewritten every launch

__device__ __forceinline__ int warp_incl_scan(int v) {
    int lane = threadIdx.x & 31;
#pragma unroll
    for (int o = 1; o < 32; o <<= 1) {
        int n = __shfl_up_sync(0xffffffffu, v, o);
        if (lane >= o) v += n;
    }
    return v;
}

// ---------------------------------------------------------------------------
// Kernel A: binarized GEMV. Packed atomic accumulate; the 37th (last) arrival
// per column publishes the final value to g_final and resets g_overlap[col].
// round(p) for p ~ U[0,1) under round-half-even == (p > 0.5f).
// ---------------------------------------------------------------------------
__global__ void __launch_bounds__(256, 4)
gemv_kernel(const float* __restrict__ p, const int* __restrict__ x) {
    __shared__ int s_act[ROWS_PER_SPLIT];
    __shared__ int s_wbase[8];
    __shared__ int s_na;

    int t    = threadIdx.x;
    int lane = t & 31;
    int w    = t >> 5;

    int r0 = blockIdx.y * ROWS_PER_SPLIT;
    int r1 = min(r0 + ROWS_PER_SPLIT, IN_DIM);
    int n  = r1 - r0;

    // per-block ordered compaction of the x slice
    int flag = 0;
    if (t < n) flag = (x[r0 + t] != 0);
    unsigned m = __ballot_sync(0xffffffffu, flag);
    int pos = __popc(m & ((1u << lane) - 1u));
    if (lane == 0) s_wbase[w] = __popc(m);
    __syncthreads();
    if (t < 8) {
        int v = s_wbase[t];
        int inc = v;
#pragma unroll
        for (int o = 1; o < 8; o <<= 1) {
            int u = __shfl_up_sync(0xffu, inc, o);
            if (t >= o) inc += u;
        }
        s_wbase[t] = inc - v;
        if (t == 7) s_na = inc;
    }
    __syncthreads();
    if (flag) s_act[s_wbase[w] + pos] = r0 + t;
    __syncthreads();

    int na = s_na;
    int col = (blockIdx.x * blockDim.x + t) * 4;
    const float4* pc = reinterpret_cast<const float4*>(p + col);

    unsigned c0 = 0, c1 = 0, c2 = 0, c3 = 0;
    int r = 0;
    for (; r + 8 <= na; r += 8) {
        float4 v[8];
#pragma unroll
        for (int u = 0; u < 8; u++)
            v[u] = __ldcs(pc + (size_t)s_act[r + u] * (OUT_DIM / 4));
#pragma unroll
        for (int u = 0; u < 8; u++) {
            c0 += (v[u].x > 0.5f);
            c1 += (v[u].y > 0.5f);
            c2 += (v[u].z > 0.5f);
            c3 += (v[u].w > 0.5f);
        }
    }
    for (; r < na; r++) {
        float4 v0 = __ldcs(pc + (size_t)s_act[r] * (OUT_DIM / 4));
        c0 += (v0.x > 0.5f);
        c1 += (v0.y > 0.5f);
        c2 += (v0.z > 0.5f);
        c3 += (v0.w > 0.5f);
    }

    unsigned cc[4] = {c0, c1, c2, c3};
#pragma unroll
    for (int u = 0; u < 4; u++) {
        unsigned old = atomicAdd(&g_overlap[col + u], CNT_ONE + cc[u]);
        if ((old >> 20) == (ROW_SPLITS - 1)) {
            g_final[col + u]   = (int)((old & VAL_MASK) + cc[u]);
            g_overlap[col + u] = 0u;      // self-reset: this was the last toucher
        }
    }
}

// ---------------------------------------------------------------------------
// Kernel B: 256 fully independent blocks, 64 columns each. Each block
// REDUNDANTLY computes the threshold (T,R) from g_final (smem histogram +
// suffix scan), counts ties preceding its segment by direct reads (exact
// jax.lax.top_k lower-index-first semantics), and writes its output slice.
// No inter-block sync, no spin, no global state to reset.
// ---------------------------------------------------------------------------
__global__ void __launch_bounds__(256)
finalize_kernel(float* __restrict__ out) {
    __shared__ int s_hist[IN_DIM + 1];
    __shared__ int s_scan[256];
    __shared__ int s_w[8];
    __shared__ int s_T, s_R, s_pref;

    int t    = threadIdx.x;
    int lane = t & 31;
    int w    = t >> 5;
    int b    = blockIdx.x;
    int base = b * BCOLS;

    for (int i = t; i <= IN_DIM; i += 256) s_hist[i] = 0;
    __syncthreads();

    // full histogram from g_final (L2-hot, 64 values/thread)
    for (int i = t; i < OUT_DIM; i += 256)
        atomicAdd(&s_hist[g_final[i]], 1);
    __syncthreads();

    // threshold: thread t owns bins [32t, 32t+31]; t==255 also bin 8192
    int b0 = t * 32;
    int csum = 0;
#pragma unroll
    for (int k = 0; k < 32; k++) csum += s_hist[b0 + k];
    if (t == 255) csum += s_hist[IN_DIM];

    s_scan[255 - t] = csum;              // reversed → prefix scan = suffix scan
    __syncthreads();
    {
        int v = s_scan[t];
        int inc = warp_incl_scan(v);
        if (lane == 31) s_w[w] = inc;
        __syncthreads();
        if (w == 0) {
            int wv = (lane < 8) ? s_w[lane] : 0;
            int winc = warp_incl_scan(wv);
            if (lane < 8) s_w[lane] = winc;
        }
        __syncthreads();
        int add = (w > 0) ? s_w[w - 1] : 0;
        s_scan[t] = inc + add;
    }
    __syncthreads();

    int above = (t == 255) ? 0 : s_scan[254 - t];
    {
        int running = above;
        int top = (t == 255) ? IN_DIM : (b0 + 31);
        for (int v = top; v >= b0; v--) {
            int prev = running;              // count(> v)
            running += s_hist[v];            // count(>= v)
            if (prev < TOPK && running >= TOPK) {
                s_T = v;
                s_R = TOPK - prev;
            }
        }
    }
    __syncthreads();
    int T = s_T;
    int R = s_R;

    // ties at T strictly before this segment (index order)
    int cnt = 0;
    for (int i = t; i < base; i += 256)
        cnt += (g_final[i] == T);
#pragma unroll
    for (int o = 16; o; o >>= 1) cnt += __shfl_down_sync(0xffffffffu, cnt, o);
    if (lane == 0) s_w[w] = cnt;
    __syncthreads();
    if (t == 0) {
        int s = 0;
#pragma unroll
        for (int j = 0; j < 8; j++) s += s_w[j];
        s_pref = s;
    }
    __syncthreads();

    // own 64 columns: warps 0 and 1, ballot-ordered tie ranks
    int v = 0, flag = 0;
    unsigned m = 0;
    if (t < BCOLS) {
        v = g_final[base + t];
        flag = (v == T);
    }
    if (w < 2) m = __ballot_sync(0xffffffffu, flag);
    if (t == 0) s_w[0] = __popc(m);        // warp 0 tie count (for warp 1)
    __syncthreads();

    if (t < BCOLS) {
        int rank = s_pref + ((w == 1) ? s_w[0] : 0) + __popc(m & ((1u << lane) - 1u));
        float val = 0.0f;
        if (v > T) val = 1.0f;
        else if (flag && rank < R) val = 1.0f;
        out[base + t] = val;
    }
}

extern "C" void kernel_launch(void* const* d_in, const int* in_sizes, int n_in,
                              void* d_out, int out_size) {
    const int*   x = (const int*)d_in[0];
    const float* p = (const float*)d_in[1];
    if (in_sizes[0] != IN_DIM) {
        x = (const int*)d_in[1];
        p = (const float*)d_in[0];
    }
    float* out = (float*)d_out;

    dim3 grid(COL_BLOCKS, ROW_SPLITS);
    gemv_kernel<<<grid, 256>>>(p, x);
    finalize_kernel<<<BBLK, 256>>>(out);
}